// round 16
// baseline (speedup 1.0000x reference)
#include <cuda_runtime.h>
#include <cuda_bf16.h>
#include <cstdint>

// Modelev12: 2-layer LSTM, H=48, B=4096, T=512, F=64
// R15 = R14 HMMA path widened: 512 threads (4 warps/SMSP), 4x4 warp tiling
// (M-groups x N8-groups), ldmatrix.x2 B fragments, parallel head reduce.
#define TOBS   512
#define FPRED  64
#define TTOT   576
#define BATCH  4096
#define MBC    32
#define NCTA   128
#define NTHR   512

// ---- SMEM byte layout (identical to R14) ----
#define SB_A0   0
#define SB_A1   52224                    // 192*136*2
#define SB_X0   129024                   // +192*200*2
#define SB_X1   139264                   // +128*40*2
#define SB_GT   154624                   // +192*40*2 ; f32 [192][34]
#define SB_HP   180736                   // f32 [48][33]
#define SB_BI0  187072
#define SB_BI1  187840
#define SB_WL   188608
#define SMEM_BYTES 188800

#define ASTR0   272
#define ASTR1   400
#define XSTR    80

__device__ __forceinline__ uint32_t smem_u32(const void* p) {
    uint32_t a;
    asm("{ .reg .u64 t; cvta.to.shared.u64 t, %1; cvt.u32.u64 %0, t; }" : "=r"(a) : "l"(p));
    return a;
}
__device__ __forceinline__ void ldsm4(uint32_t r[4], uint32_t addr) {
    asm volatile("ldmatrix.sync.aligned.m8n8.x4.shared.b16 {%0,%1,%2,%3}, [%4];"
                 : "=r"(r[0]), "=r"(r[1]), "=r"(r[2]), "=r"(r[3]) : "r"(addr));
}
__device__ __forceinline__ void ldsm2t(uint32_t r[2], uint32_t addr) {
    asm volatile("ldmatrix.sync.aligned.m8n8.x2.trans.shared.b16 {%0,%1}, [%2];"
                 : "=r"(r[0]), "=r"(r[1]) : "r"(addr));
}
__device__ __forceinline__ void mma16816(float d[4], const uint32_t a[4], const uint32_t b[2]) {
    asm volatile("mma.sync.aligned.m16n8k16.row.col.f32.bf16.bf16.f32 "
                 "{%0,%1,%2,%3}, {%4,%5,%6,%7}, {%8,%9}, {%0,%1,%2,%3};"
                 : "+f"(d[0]), "+f"(d[1]), "+f"(d[2]), "+f"(d[3])
                 : "r"(a[0]), "r"(a[1]), "r"(a[2]), "r"(a[3]), "r"(b[0]), "r"(b[1]));
}
__device__ __forceinline__ float fsig(float xv) {
    float e = __expf(-xv);
    return __fdividef(1.0f, 1.0f + e);
}
__device__ __forceinline__ float ftanh(float xv) {
    float a = fabsf(xv);
    float e = __expf(-2.0f * a);
    float r = __fdividef(1.0f - e, 1.0f + e);
    return copysignf(r, xv);
}
__device__ __forceinline__ unsigned short bfhi(float v) {
    __nv_bfloat16 h = __float2bfloat16(v);
    return *(unsigned short*)&h;
}
__device__ __forceinline__ unsigned short bflo(float v) {
    __nv_bfloat16 h = __float2bfloat16(v);
    __nv_bfloat16 l = __float2bfloat16(v - __bfloat162float(h));
    return *(unsigned short*)&l;
}
__device__ __forceinline__ float w0cat(const float* wih0, const float* whh0, int r, int k) {
    if (k == 0) return wih0[r];
    if (k < 49) return whh0[r * 48 + (k - 1)];
    return 0.0f;
}
__device__ __forceinline__ float w1cat(const float* wih1, const float* whh1, int r, int k) {
    if (k < 48)  return wih1[r * 48 + k];
    if (k < 96)  return whh1[r * 48 + (k - 48)];
    return 0.0f;
}

__global__ void __launch_bounds__(NTHR, 1) lstm576_hmma2_kernel(
    const float* __restrict__ x,
    const float* __restrict__ wih0, const float* __restrict__ whh0,
    const float* __restrict__ bih0, const float* __restrict__ bhh0,
    const float* __restrict__ wih1, const float* __restrict__ whh1,
    const float* __restrict__ bih1, const float* __restrict__ bhh1,
    const float* __restrict__ wlin, const float* __restrict__ blin,
    float* __restrict__ out)
{
    extern __shared__ char smem[];
    const uint32_t sb = smem_u32(smem);
    const int tid  = threadIdx.x, lane = tid & 31, wid = tid >> 5;
    const int gb0  = blockIdx.x * MBC;

    unsigned short* A0u = (unsigned short*)(smem + SB_A0);
    unsigned short* A1u = (unsigned short*)(smem + SB_A1);
    unsigned short* X0u = (unsigned short*)(smem + SB_X0);
    unsigned short* X1u = (unsigned short*)(smem + SB_X1);
    float* GT  = (float*)(smem + SB_GT);
    float* HP  = (float*)(smem + SB_HP);
    float* BI0 = (float*)(smem + SB_BI0);
    float* BI1 = (float*)(smem + SB_BI1);
    float* WLs = (float*)(smem + SB_WL);

    // ---- one-time staging ----
    for (int i = tid; i < 192 * 136; i += NTHR) {
        int r = i / 136, c = i - r * 136;
        unsigned short v = 0;
        if (c < 64)       v = bfhi(w0cat(wih0, whh0, r, c));
        else if (c < 128) v = bflo(w0cat(wih0, whh0, r, c - 64));
        A0u[i] = v;
    }
    for (int i = tid; i < 192 * 200; i += NTHR) {
        int r = i / 200, c = i - r * 200;
        unsigned short v = 0;
        if (c < 96)       v = bfhi(w1cat(wih1, whh1, r, c));
        else if (c < 192) v = bflo(w1cat(wih1, whh1, r, c - 96));
        A1u[i] = v;
    }
    for (int i = tid; i < 128 * 40; i += NTHR) X0u[i] = 0;
    for (int i = tid; i < 192 * 40; i += NTHR) X1u[i] = 0;
    for (int i = tid; i < 192; i += NTHR) {
        BI0[i] = bih0[i] + bhh0[i];
        BI1[i] = bih1[i] + bhh1[i];
    }
    if (tid < 48) WLs[tid] = wlin[tid];
    __syncthreads();
    if (tid < 32) {
        float v = x[(size_t)(gb0 + tid) * TOBS];
        X0u[tid]            = bfhi(v);   // row 0 (x hi)
        X0u[64 * 40 + tid]  = bflo(v);   // row 64 (x lo)
    }
    const float blv = blin[0];

    // warp tiling: mw -> m-tiles {mw, mw+4, mw+8}; nq -> 8-col group
    const int mw = wid & 3, nq = wid >> 2, n0 = nq * 8;
    const int trow = lane & 7, tg = lane >> 3;
    const int off1 = (tg & 1) * 8;     // m-offset (A)
    const int off2 = (tg >> 1) * 8;    // k-offset (A)
    const int brow = ((lane >> 3) & 1) * 8 + trow;   // B x2 source row
    const int gid  = lane >> 2, ctid = lane & 3;

    // head mapping: 16 threads per batch
    const int hb = tid >> 4, hk = (tid & 15) * 3;

    float c0[3], c1[3];
#pragma unroll
    for (int i = 0; i < 3; i++) { c0[i] = 0.0f; c1[i] = 0.0f; }

    __syncthreads();

    for (int t = 0; t < TTOT; t++) {
        float xn = 0.0f;
        if ((tid & 15) == 0 && (t + 1) < TOBS)
            xn = x[(size_t)(gb0 + hb) * TOBS + (t + 1)];

        // ======== GEMM0: gates0 = W0cat @ X0cat ========
        {
            float d[3][4];
#pragma unroll
            for (int a = 0; a < 3; a++)
#pragma unroll
                for (int q = 0; q < 4; q++) d[a][q] = 0.0f;
#pragma unroll
            for (int ks = 0; ks < 4; ks++) {
                int kb = ks * 16;
                uint32_t bh[2], bl[2];
                uint32_t baddr = sb + SB_X0 + (uint32_t)((kb + brow) * XSTR + n0 * 2);
                ldsm2t(bh, baddr);
                ldsm2t(bl, baddr + 64 * XSTR);   // Xlo rows +64
#pragma unroll
                for (int mt = 0; mt < 3; mt++) {
                    int m0 = (mw + mt * 4) * 16;
                    uint32_t aaddr = sb + SB_A0 + (uint32_t)((m0 + off1 + trow) * ASTR0 + (kb + off2) * 2);
                    uint32_t ah[4], al[4];
                    ldsm4(ah, aaddr);
                    ldsm4(al, aaddr + 128);      // Wlo cols +64 (*2B)
                    mma16816(d[mt], ah, bh);
                    mma16816(d[mt], ah, bl);
                    mma16816(d[mt], al, bh);
                }
            }
#pragma unroll
            for (int mt = 0; mt < 3; mt++) {
                int m0 = (mw + mt * 4) * 16;
                *(float2*)(GT + (m0 + gid) * 34 + n0 + 2 * ctid)     = make_float2(d[mt][0], d[mt][1]);
                *(float2*)(GT + (m0 + gid + 8) * 34 + n0 + 2 * ctid) = make_float2(d[mt][2], d[mt][3]);
            }
        }
        __syncthreads();

        // ======== act0 -> h0 splits into X1 (rows j / 96+j) and X0 (rows 1+j / 65+j) ========
#pragma unroll
        for (int i = 0; i < 3; i++) {
            int e = tid + NTHR * i, b = e & 31, j = e >> 5;
            float gi = GT[j * 34 + b]          + BI0[j];
            float gf = GT[(48 + j) * 34 + b]   + BI0[48 + j];
            float gg = GT[(96 + j) * 34 + b]   + BI0[96 + j];
            float go = GT[(144 + j) * 34 + b]  + BI0[144 + j];
            float c = fmaf(fsig(gf), c0[i], fsig(gi) * ftanh(gg));
            c0[i] = c;
            float h = fsig(go) * ftanh(c);
            unsigned short hh = bfhi(h), hl = bflo(h);
            X1u[j * 40 + b]          = hh;
            X1u[(96 + j) * 40 + b]   = hl;
            X0u[(1 + j) * 40 + b]    = hh;
            X0u[(65 + j) * 40 + b]   = hl;
        }
        __syncthreads();

        // ======== GEMM1: gates1 = W1cat @ X1cat ========
        {
            float d[3][4];
#pragma unroll
            for (int a = 0; a < 3; a++)
#pragma unroll
                for (int q = 0; q < 4; q++) d[a][q] = 0.0f;
#pragma unroll
            for (int ks = 0; ks < 6; ks++) {
                int kb = ks * 16;
                uint32_t bh[2], bl[2];
                uint32_t baddr = sb + SB_X1 + (uint32_t)((kb + brow) * XSTR + n0 * 2);
                ldsm2t(bh, baddr);
                ldsm2t(bl, baddr + 96 * XSTR);   // Xlo rows +96
#pragma unroll
                for (int mt = 0; mt < 3; mt++) {
                    int m0 = (mw + mt * 4) * 16;
                    uint32_t aaddr = sb + SB_A1 + (uint32_t)((m0 + off1 + trow) * ASTR1 + (kb + off2) * 2);
                    uint32_t ah[4], al[4];
                    ldsm4(ah, aaddr);
                    ldsm4(al, aaddr + 192);      // Wlo cols +96 (*2B)
                    mma16816(d[mt], ah, bh);
                    mma16816(d[mt], ah, bl);
                    mma16816(d[mt], al, bh);
                }
            }
#pragma unroll
            for (int mt = 0; mt < 3; mt++) {
                int m0 = (mw + mt * 4) * 16;
                *(float2*)(GT + (m0 + gid) * 34 + n0 + 2 * ctid)     = make_float2(d[mt][0], d[mt][1]);
                *(float2*)(GT + (m0 + gid + 8) * 34 + n0 + 2 * ctid) = make_float2(d[mt][2], d[mt][3]);
            }
        }
        __syncthreads();

        // ======== act1 -> h1 splits into X1 (rows 48+j / 144+j) + head partials ========
#pragma unroll
        for (int i = 0; i < 3; i++) {
            int e = tid + NTHR * i, b = e & 31, j = e >> 5;
            float gi = GT[j * 34 + b]          + BI1[j];
            float gf = GT[(48 + j) * 34 + b]   + BI1[48 + j];
            float gg = GT[(96 + j) * 34 + b]   + BI1[96 + j];
            float go = GT[(144 + j) * 34 + b]  + BI1[144 + j];
            float c = fmaf(fsig(gf), c1[i], fsig(gi) * ftanh(gg));
            c1[i] = c;
            float h = fsig(go) * ftanh(c);
            X1u[(48 + j) * 40 + b]   = bfhi(h);
            X1u[(144 + j) * 40 + b]  = bflo(h);
            HP[j * 33 + b] = h * WLs[j];
        }
        __syncthreads();

        // ======== head: 16 threads per batch, shfl reduce ========
        {
            float s = HP[hk * 33 + hb] + HP[(hk + 1) * 33 + hb] + HP[(hk + 2) * 33 + hb];
            s += __shfl_xor_sync(0xFFFFFFFFu, s, 1);
            s += __shfl_xor_sync(0xFFFFFFFFu, s, 2);
            s += __shfl_xor_sync(0xFFFFFFFFu, s, 4);
            s += __shfl_xor_sync(0xFFFFFFFFu, s, 8);
            if ((tid & 15) == 0) {
                s += blv;
                out[(size_t)(gb0 + hb) * TTOT + t] = s;
                float nx = ((t + 1) < TOBS) ? xn : s;
                X0u[hb]           = bfhi(nx);
                X0u[64 * 40 + hb] = bflo(nx);
            }
        }
        __syncthreads();
    }
}

extern "C" void kernel_launch(void* const* d_in, const int* in_sizes, int n_in,
                              void* d_out, int out_size)
{
    (void)in_sizes; (void)n_in; (void)out_size;
    const float* x    = (const float*)d_in[0];
    const float* wih0 = (const float*)d_in[1];
    const float* whh0 = (const float*)d_in[2];
    const float* bih0 = (const float*)d_in[3];
    const float* bhh0 = (const float*)d_in[4];
    const float* wih1 = (const float*)d_in[5];
    const float* whh1 = (const float*)d_in[6];
    const float* bih1 = (const float*)d_in[7];
    const float* bhh1 = (const float*)d_in[8];
    const float* wlin = (const float*)d_in[9];
    const float* blin = (const float*)d_in[10];
    float* out = (float*)d_out;

    cudaFuncSetAttribute(lstm576_hmma2_kernel,
                         cudaFuncAttributeMaxDynamicSharedMemorySize, SMEM_BYTES);
    lstm576_hmma2_kernel<<<NCTA, NTHR, SMEM_BYTES>>>(
        x, wih0, whh0, bih0, bhh0, wih1, whh1, bih1, bhh1, wlin, blin, out);
}

// round 17
// speedup vs baseline: 1.4942x; 1.4942x over previous
#include <cuda_runtime.h>
#include <cuda_bf16.h>
#include <cstdint>

// Modelev12: 2-layer LSTM, H=48, B=4096, T=512, F=64
// R16 = R14 HMMA core split into two skewed 128-thread clusters (16 batches
// each; one warp per cluster per SMSP) + tanh.approx activations.
//  - cluster A = warps 0..3, cluster B = warps 4..7 (SMSP = wid&3)
//  - named barriers bar.sync cl+1,128 ; cluster B half-step skewed so
//    tensor(GEMM) of one cluster overlaps MUFU(act) of the other.
//  - fragment mappings identical to the verified R14 kernel.
#define TOBS   512
#define FPRED  64
#define TTOT   576
#define BATCH  4096
#define MBC    32
#define NCTA   128
#define NTHR   256
#define NSKEW  650

typedef unsigned long long ull;
__device__ unsigned int g_skew_sink[NCTA * NTHR];

// ---- SMEM byte layout ----
// A0: bf16 [192][136] stride 272B (cols 0-63 Whi, 64-127 Wlo)
// A1: bf16 [192][200] stride 400B (cols 0-95 Whi, 96-191 Wlo)
// Per cluster (x2):
//   X0: bf16 [128][24] stride 48B (rows 0-63 hi: 0=x,1-48=h0; 64-127 lo)
//   X1: bf16 [192][24] stride 48B (rows 0-95 hi: h0|h1; 96-191 lo)
//   GT: f32 [192][18] ; HP: f32 [48][17]
#define SB_A0   0
#define SB_A1   52224
#define SB_X0   129024
#define X0_CL   6144
#define SB_X1   141312
#define X1_CL   9216
#define SB_GT   159744
#define GT_CL   13824
#define SB_HP   187392
#define HP_CL   3264
#define SB_BI0  193920
#define SB_BI1  194688
#define SB_WL   195456
#define SMEM_BYTES 195648

#define ASTR0   272
#define ASTR1   400
#define XSTRB   48      // X row stride bytes
#define XSTRU   24      // X row stride in u16

__device__ __forceinline__ uint32_t smem_u32(const void* p) {
    uint32_t a;
    asm("{ .reg .u64 t; cvta.to.shared.u64 t, %1; cvt.u32.u64 %0, t; }" : "=r"(a) : "l"(p));
    return a;
}
__device__ __forceinline__ void ldsm4(uint32_t r[4], uint32_t addr) {
    asm volatile("ldmatrix.sync.aligned.m8n8.x4.shared.b16 {%0,%1,%2,%3}, [%4];"
                 : "=r"(r[0]), "=r"(r[1]), "=r"(r[2]), "=r"(r[3]) : "r"(addr));
}
__device__ __forceinline__ void ldsm4t(uint32_t r[4], uint32_t addr) {
    asm volatile("ldmatrix.sync.aligned.m8n8.x4.trans.shared.b16 {%0,%1,%2,%3}, [%4];"
                 : "=r"(r[0]), "=r"(r[1]), "=r"(r[2]), "=r"(r[3]) : "r"(addr));
}
__device__ __forceinline__ void mma16816(float d[4], const uint32_t a[4], const uint32_t b[2]) {
    asm volatile("mma.sync.aligned.m16n8k16.row.col.f32.bf16.bf16.f32 "
                 "{%0,%1,%2,%3}, {%4,%5,%6,%7}, {%8,%9}, {%0,%1,%2,%3};"
                 : "+f"(d[0]), "+f"(d[1]), "+f"(d[2]), "+f"(d[3])
                 : "r"(a[0]), "r"(a[1]), "r"(a[2]), "r"(a[3]), "r"(b[0]), "r"(b[1]));
}
__device__ __forceinline__ float ftanha(float xv) {
    float r; asm("tanh.approx.f32 %0, %1;" : "=f"(r) : "f"(xv)); return r;
}
__device__ __forceinline__ float fsiga(float xv) {
    return fmaf(ftanha(0.5f * xv), 0.5f, 0.5f);
}
__device__ __forceinline__ unsigned short bfhi(float v) {
    __nv_bfloat16 h = __float2bfloat16(v);
    return *(unsigned short*)&h;
}
__device__ __forceinline__ unsigned short bflo(float v) {
    __nv_bfloat16 h = __float2bfloat16(v);
    __nv_bfloat16 l = __float2bfloat16(v - __bfloat162float(h));
    return *(unsigned short*)&l;
}
__device__ __forceinline__ float w0cat(const float* wih0, const float* whh0, int r, int k) {
    if (k == 0) return wih0[r];
    if (k < 49) return whh0[r * 48 + (k - 1)];
    return 0.0f;
}
__device__ __forceinline__ float w1cat(const float* wih1, const float* whh1, int r, int k) {
    if (k < 48)  return wih1[r * 48 + k];
    if (k < 96)  return whh1[r * 48 + (k - 48)];
    return 0.0f;
}
#define CBAR() asm volatile("bar.sync %0, 128;" :: "r"(cl + 1) : "memory")

__global__ void __launch_bounds__(NTHR, 1) lstm576_hmma3_kernel(
    const float* __restrict__ x,
    const float* __restrict__ wih0, const float* __restrict__ whh0,
    const float* __restrict__ bih0, const float* __restrict__ bhh0,
    const float* __restrict__ wih1, const float* __restrict__ whh1,
    const float* __restrict__ bih1, const float* __restrict__ bhh1,
    const float* __restrict__ wlin, const float* __restrict__ blin,
    float* __restrict__ out)
{
    extern __shared__ char smem[];
    const uint32_t sb = smem_u32(smem);
    const int tid  = threadIdx.x, lane = tid & 31, wid = tid >> 5;
    const int cl   = wid >> 2;            // cluster 0 (warps 0-3) / 1 (warps 4-7)
    const int mw   = wid & 3;             // m-group within cluster (also SMSP id)
    const int tcl  = (cl == 0) ? tid : (tid - 128);   // thread-in-cluster
    const int gb0  = blockIdx.x * MBC;
    const int gbc  = gb0 + cl * 16;       // cluster batch base

    unsigned short* A0u = (unsigned short*)(smem + SB_A0);
    unsigned short* A1u = (unsigned short*)(smem + SB_A1);
    unsigned short* X0u = (unsigned short*)(smem + SB_X0 + cl * X0_CL);
    unsigned short* X1u = (unsigned short*)(smem + SB_X1 + cl * X1_CL);
    float* GTc = (float*)(smem + SB_GT + cl * GT_CL);
    float* HPc = (float*)(smem + SB_HP + cl * HP_CL);
    float* BI0 = (float*)(smem + SB_BI0);
    float* BI1 = (float*)(smem + SB_BI1);
    float* WLs = (float*)(smem + SB_WL);

    // ---- one-time staging (block-wide) ----
    for (int i = tid; i < 192 * 136; i += NTHR) {
        int r = i / 136, c = i - r * 136;
        unsigned short v = 0;
        if (c < 64)       v = bfhi(w0cat(wih0, whh0, r, c));
        else if (c < 128) v = bflo(w0cat(wih0, whh0, r, c - 64));
        A0u[i] = v;
    }
    for (int i = tid; i < 192 * 200; i += NTHR) {
        int r = i / 200, c = i - r * 200;
        unsigned short v = 0;
        if (c < 96)       v = bfhi(w1cat(wih1, whh1, r, c));
        else if (c < 192) v = bflo(w1cat(wih1, whh1, r, c - 96));
        A1u[i] = v;
    }
    for (int i = tid; i < 2 * X0_CL / 2; i += NTHR) ((unsigned short*)(smem + SB_X0))[i] = 0;
    for (int i = tid; i < 2 * X1_CL / 2; i += NTHR) ((unsigned short*)(smem + SB_X1))[i] = 0;
    for (int i = tid; i < 192; i += NTHR) {
        BI0[i] = bih0[i] + bhh0[i];
        BI1[i] = bih1[i] + bhh1[i];
    }
    if (tid < 48) WLs[tid] = wlin[tid];
    __syncthreads();
    if (tid < 32) {   // x(0): tid = cl*16 + b
        float v = x[(size_t)(gb0 + tid) * TOBS];
        unsigned short* Xc = (unsigned short*)(smem + SB_X0 + (tid >> 4) * X0_CL);
        Xc[tid & 15]                 = bfhi(v);
        Xc[64 * XSTRU + (tid & 15)]  = bflo(v);
    }
    const float blv = blin[0];

    // fragment-lane constants (identical to R14)
    const int trow = lane & 7, tg = lane >> 3;
    const int off1 = (tg & 1) * 8;       // m-offset (A) / k-offset (B)
    const int off2 = (tg >> 1) * 8;      // k-offset (A) / n-offset (B)
    const int gid  = lane >> 2, ctid = lane & 3;
    // head: 8 threads per batch
    const int hb = tcl >> 3, hk = (tcl & 7) * 6;

    float c0[6], c1[6];
#pragma unroll
    for (int i = 0; i < 6; i++) { c0[i] = 0.0f; c1[i] = 0.0f; }

    __syncthreads();   // staging complete; clusters now independent

    if (cl == 1) {     // half-step skew
        unsigned int v = (unsigned int)(tid * 2654435761u + blockIdx.x);
#pragma unroll 1
        for (int i = 0; i < NSKEW; i++) v = v * 1664525u + 1013904223u;
        g_skew_sink[blockIdx.x * NTHR + tid] = v;
    }

    for (int t = 0; t < TTOT; t++) {
        float xn = 0.0f;
        if ((tcl & 7) == 0 && (t + 1) < TOBS)
            xn = x[(size_t)(gbc + hb) * TOBS + (t + 1)];

        // ======== GEMM0: gates0 = W0cat @ X0cat ========
        {
            float d[3][2][4];
#pragma unroll
            for (int a = 0; a < 3; a++)
#pragma unroll
                for (int b = 0; b < 2; b++)
#pragma unroll
                    for (int q = 0; q < 4; q++) d[a][b][q] = 0.0f;
#pragma unroll
            for (int ks = 0; ks < 4; ks++) {
                int kb = ks * 16;
                uint32_t bh[4], bl[4];
                uint32_t baddr = sb + SB_X0 + (uint32_t)(cl * X0_CL)
                               + (uint32_t)((kb + off1 + trow) * XSTRB + off2 * 2);
                ldsm4t(bh, baddr);
                ldsm4t(bl, baddr + 64 * XSTRB);
#pragma unroll
                for (int mt = 0; mt < 3; mt++) {
                    int m0 = (mw + mt * 4) * 16;
                    uint32_t aaddr = sb + SB_A0 + (uint32_t)((m0 + off1 + trow) * ASTR0 + (kb + off2) * 2);
                    uint32_t ah[4], al[4];
                    ldsm4(ah, aaddr);
                    ldsm4(al, aaddr + 128);
                    mma16816(d[mt][0], ah, &bh[0]);
                    mma16816(d[mt][0], ah, &bl[0]);
                    mma16816(d[mt][0], al, &bh[0]);
                    mma16816(d[mt][1], ah, &bh[2]);
                    mma16816(d[mt][1], ah, &bl[2]);
                    mma16816(d[mt][1], al, &bh[2]);
                }
            }
#pragma unroll
            for (int mt = 0; mt < 3; mt++) {
                int m0 = (mw + mt * 4) * 16;
#pragma unroll
                for (int nt = 0; nt < 2; nt++) {
                    int cb = nt * 8 + 2 * ctid;
                    *(float2*)(GTc + (m0 + gid) * 18 + cb)     = make_float2(d[mt][nt][0], d[mt][nt][1]);
                    *(float2*)(GTc + (m0 + gid + 8) * 18 + cb) = make_float2(d[mt][nt][2], d[mt][nt][3]);
                }
            }
        }
        CBAR();

        // ======== act0 -> h0 splits into X1 (rows j/96+j) and X0 (rows 1+j/65+j) ========
#pragma unroll
        for (int i = 0; i < 6; i++) {
            int e = tcl + 128 * i, b = e & 15, j = e >> 4;
            float gi = GTc[j * 18 + b]          + BI0[j];
            float gf = GTc[(48 + j) * 18 + b]   + BI0[48 + j];
            float gg = GTc[(96 + j) * 18 + b]   + BI0[96 + j];
            float go = GTc[(144 + j) * 18 + b]  + BI0[144 + j];
            float c = fmaf(fsiga(gf), c0[i], fsiga(gi) * ftanha(gg));
            c0[i] = c;
            float h = fsiga(go) * ftanha(c);
            unsigned short hh = bfhi(h), hl = bflo(h);
            X1u[j * XSTRU + b]          = hh;
            X1u[(96 + j) * XSTRU + b]   = hl;
            X0u[(1 + j) * XSTRU + b]    = hh;
            X0u[(65 + j) * XSTRU + b]   = hl;
        }
        CBAR();

        // ======== GEMM1: gates1 = W1cat @ X1cat ========
        {
            float d[3][2][4];
#pragma unroll
            for (int a = 0; a < 3; a++)
#pragma unroll
                for (int b = 0; b < 2; b++)
#pragma unroll
                    for (int q = 0; q < 4; q++) d[a][b][q] = 0.0f;
#pragma unroll
            for (int ks = 0; ks < 6; ks++) {
                int kb = ks * 16;
                uint32_t bh[4], bl[4];
                uint32_t baddr = sb + SB_X1 + (uint32_t)(cl * X1_CL)
                               + (uint32_t)((kb + off1 + trow) * XSTRB + off2 * 2);
                ldsm4t(bh, baddr);
                ldsm4t(bl, baddr + 96 * XSTRB);
#pragma unroll
                for (int mt = 0; mt < 3; mt++) {
                    int m0 = (mw + mt * 4) * 16;
                    uint32_t aaddr = sb + SB_A1 + (uint32_t)((m0 + off1 + trow) * ASTR1 + (kb + off2) * 2);
                    uint32_t ah[4], al[4];
                    ldsm4(ah, aaddr);
                    ldsm4(al, aaddr + 192);
                    mma16816(d[mt][0], ah, &bh[0]);
                    mma16816(d[mt][0], ah, &bl[0]);
                    mma16816(d[mt][0], al, &bh[0]);
                    mma16816(d[mt][1], ah, &bh[2]);
                    mma16816(d[mt][1], ah, &bl[2]);
                    mma16816(d[mt][1], al, &bh[2]);
                }
            }
#pragma unroll
            for (int mt = 0; mt < 3; mt++) {
                int m0 = (mw + mt * 4) * 16;
#pragma unroll
                for (int nt = 0; nt < 2; nt++) {
                    int cb = nt * 8 + 2 * ctid;
                    *(float2*)(GTc + (m0 + gid) * 18 + cb)     = make_float2(d[mt][nt][0], d[mt][nt][1]);
                    *(float2*)(GTc + (m0 + gid + 8) * 18 + cb) = make_float2(d[mt][nt][2], d[mt][nt][3]);
                }
            }
        }
        CBAR();

        // ======== act1 -> h1 splits into X1 (rows 48+j/144+j) + head partials ========
#pragma unroll
        for (int i = 0; i < 6; i++) {
            int e = tcl + 128 * i, b = e & 15, j = e >> 4;
            float gi = GTc[j * 18 + b]          + BI1[j];
            float gf = GTc[(48 + j) * 18 + b]   + BI1[48 + j];
            float gg = GTc[(96 + j) * 18 + b]   + BI1[96 + j];
            float go = GTc[(144 + j) * 18 + b]  + BI1[144 + j];
            float c = fmaf(fsiga(gf), c1[i], fsiga(gi) * ftanha(gg));
            c1[i] = c;
            float h = fsiga(go) * ftanha(c);
            X1u[(48 + j) * XSTRU + b]   = bfhi(h);
            X1u[(144 + j) * XSTRU + b]  = bflo(h);
            HPc[j * 17 + b] = h * WLs[j];
        }
        CBAR();

        // ======== head: 8 threads per batch, shfl reduce ========
        {
            float s = 0.0f;
#pragma unroll
            for (int k = 0; k < 6; k++) s += HPc[(hk + k) * 17 + hb];
            s += __shfl_xor_sync(0xFFFFFFFFu, s, 1);
            s += __shfl_xor_sync(0xFFFFFFFFu, s, 2);
            s += __shfl_xor_sync(0xFFFFFFFFu, s, 4);
            if ((tcl & 7) == 0) {
                s += blv;
                out[(size_t)(gbc + hb) * TTOT + t] = s;
                float nx = ((t + 1) < TOBS) ? xn : s;
                X0u[hb]              = bfhi(nx);
                X0u[64 * XSTRU + hb] = bflo(nx);
            }
        }
        CBAR();
    }
}

extern "C" void kernel_launch(void* const* d_in, const int* in_sizes, int n_in,
                              void* d_out, int out_size)
{
    (void)in_sizes; (void)n_in; (void)out_size;
    const float* x    = (const float*)d_in[0];
    const float* wih0 = (const float*)d_in[1];
    const float* whh0 = (const float*)d_in[2];
    const float* bih0 = (const float*)d_in[3];
    const float* bhh0 = (const float*)d_in[4];
    const float* wih1 = (const float*)d_in[5];
    const float* whh1 = (const float*)d_in[6];
    const float* bih1 = (const float*)d_in[7];
    const float* bhh1 = (const float*)d_in[8];
    const float* wlin = (const float*)d_in[9];
    const float* blin = (const float*)d_in[10];
    float* out = (float*)d_out;

    cudaFuncSetAttribute(lstm576_hmma3_kernel,
                         cudaFuncAttributeMaxDynamicSharedMemorySize, SMEM_BYTES);
    lstm576_hmma3_kernel<<<NCTA, NTHR, SMEM_BYTES>>>(
        x, wih0, whh0, bih0, bhh0, wih1, whh1, bih1, bhh1, wlin, blin, out);
}